// round 7
// baseline (speedup 1.0000x reference)
#include <cuda_runtime.h>
#include <cstdint>
#include <cstddef>

// Problem constants (fixed by the reference: B=64, T=512, S=16, NZ=512)
#define BB 64
#define TT 512
#define SS 16
#define NZ 512

// Output layout (float32, concatenated flattened reference outputs):
//   cell_input      : [B, T, NZ]     at offset 0
//   reset_input     : [B, T, 2*NZ]   at offset B*T*NZ
//   reset_indicator : [B, T]         at offset B*T*3*NZ   (written as 0.0f / 1.0f)

__device__ __forceinline__ uint32_t smem_u32(const void* p) {
    uint32_t a;
    asm("{ .reg .u64 tmp; cvta.to.shared.u64 tmp, %1; cvt.u32.u64 %0, tmp; }"
        : "=r"(a) : "l"(p));
    return a;
}

__device__ __forceinline__ bool elect_one() {
    uint32_t pred;
    asm volatile(
        "{\n\t"
        ".reg .pred p;\n\t"
        "elect.sync _|p, 0xFFFFFFFF;\n\t"
        "selp.b32 %0, 1, 0, p;\n\t"
        "}" : "=r"(pred));
    return pred != 0;
}

__global__ __launch_bounds__(NZ / 4, 8)
void soft2frames_kernel(const float* __restrict__ seg_start,  // [S, B]
                        const float* __restrict__ seg_end,    // [S, B]
                        const float* __restrict__ e0_seg,     // [S, B, NZ]
                        const float* __restrict__ eg_seg,     // [S, B, NZ]
                        float* __restrict__ out) {
    const int t   = blockIdx.x;   // 0..T-1
    const int b   = blockIdx.y;   // 0..B-1
    const int tid = threadIdx.x;  // 0..127, one float4 lane of NZ

    __shared__ __align__(16) float4 sm_cell[NZ / 4];        // 2048 B
    __shared__ __align__(16) float4 sm_rst[NZ / 2];         // 4096 B: [g | e]
    __shared__ int   sh_sel;
    __shared__ int   sh_ind;
    __shared__ float sh_inter;

    // ---- segment selection: one warp, one lane per segment ----
    if (tid < 32) {
        float ss = 0.f, se = 0.f;
        int inr = 0, hit = 0;
        if (tid < SS) {
            ss = __ldg(&seg_start[tid * BB + b]);
            se = __ldg(&seg_end[tid * BB + b]);
            const int cs = (int)ceilf(ss);
            const int fe = (int)floorf(se);
            inr = (t >= cs) & (t <= fe);
            hit = (min(max(cs, 0), TT - 1) == t);
        }
        const unsigned mc = __ballot_sync(0xffffffffu, inr);
        const unsigned mi = __ballot_sync(0xffffffffu, hit);
        const int sel = 31 - __clz(mc);            // last segment wins; -1 if uncovered
        const float st = __shfl_sync(0xffffffffu, ss, sel & 31);
        const float en = __shfl_sync(0xffffffffu, se, sel & 31);
        if (tid == 0) {
            sh_sel   = sel;
            sh_ind   = (mi != 0u);
            sh_inter = ((float)t - st) / (en - st + 1e-7f);
        }
    }
    __syncthreads();

    const int   sel   = sh_sel;
    const float inter = sh_inter;
    const size_t bt   = (size_t)b * TT + t;

    // ---- compute tile into SMEM ----
    if (sel >= 0) {
        const size_t base = ((size_t)sel * BB + b) * NZ;
        const float4 e = __ldg((const float4*)(e0_seg + base) + tid);
        const float4 g = __ldg((const float4*)(eg_seg + base) + tid);
        float4 c;
        c.x = fmaf(g.x - e.x, inter, e.x);
        c.y = fmaf(g.y - e.y, inter, e.y);
        c.z = fmaf(g.z - e.z, inter, e.z);
        c.w = fmaf(g.w - e.w, inter, e.w);
        sm_cell[tid]          = c;   // cell_input row
        sm_rst[tid]           = g;   // reset_input[:, :NZ] = e_gs
        sm_rst[tid + NZ / 4]  = e;   // reset_input[:, NZ:] = e_0s
    } else {
        const float4 z = make_float4(0.f, 0.f, 0.f, 0.f);
        sm_cell[tid]         = z;
        sm_rst[tid]          = z;
        sm_rst[tid + NZ / 4] = z;
    }

    // reset_indicator: plain STG, outside the async-proxy window
    if (tid == 64) {
        out[(size_t)BB * TT * 3 * NZ + bt] = (float)sh_ind;
    }
    __syncthreads();

    // ---- bulk stores: SMEM -> GMEM via async proxy (bypass per-warp STG path) ----
    if (tid < 32) {
        if (elect_one()) {
            asm volatile("fence.proxy.async.shared::cta;" ::: "memory");
            float* cell_dst = out + bt * NZ;
            float* rst_dst  = out + (size_t)BB * TT * NZ + bt * (2 * NZ);
            const uint32_t sm_cell_a = smem_u32(sm_cell);
            const uint32_t sm_rst_a  = smem_u32(sm_rst);
            asm volatile("cp.async.bulk.global.shared::cta.bulk_group [%0], [%1], %2;"
                         :: "l"(cell_dst), "r"(sm_cell_a), "r"((uint32_t)(NZ * 4)) : "memory");
            asm volatile("cp.async.bulk.global.shared::cta.bulk_group [%0], [%1], %2;"
                         :: "l"(rst_dst), "r"(sm_rst_a), "r"((uint32_t)(2 * NZ * 4)) : "memory");
            asm volatile("cp.async.bulk.commit_group;" ::: "memory");
            asm volatile("cp.async.bulk.wait_group 0;" ::: "memory");
        }
    }
}

extern "C" void kernel_launch(void* const* d_in, const int* in_sizes, int n_in,
                              void* d_out, int out_size) {
    const float* seg_start = (const float*)d_in[0];
    const float* seg_end   = (const float*)d_in[1];
    const float* e0_seg    = (const float*)d_in[2];
    const float* eg_seg    = (const float*)d_in[3];
    float* out = (float*)d_out;

    dim3 grid(TT, BB);
    soft2frames_kernel<<<grid, NZ / 4>>>(seg_start, seg_end, e0_seg, eg_seg, out);
}